// round 9
// baseline (speedup 1.0000x reference)
#include <cuda_runtime.h>
#include <math.h>

// Problem constants
#define BN    64
#define HW    784           // 28*28
#define CN    512
#define SA    28            // argmax hw splits  (HWPA = 28)
#define HWPA  28
#define SB    7             // apply hw splits   (HWPB = 112)
#define HWPB  112
#define CT    4             // channel tiles in apply
#define CPB   128           // channels per apply block
#define PAD   113           // smem row pitch (gcd(113,32)=1 -> conflict-free)
#define HWS   28            // hw per thread in apply phase B

// Scratch (device globals: allocation-free)
__device__ float g_pval[BN * SA * CN];
__device__ int   g_pidx[BN * SA * CN];
__device__ int   g_idx [BN * CN];

// ---------------------------------------------------------------------------
// Kernel 1: partial argmax (proven: 19.5us, DRAM 67%).
// ---------------------------------------------------------------------------
__global__ void __launch_bounds__(CN)
argmax_partial_kernel(const float* __restrict__ x) {
    const int s = blockIdx.x;
    const int b = blockIdx.y;
    const int c = threadIdx.x;
    const int hw0 = s * HWPA;

    const size_t base = ((size_t)b * HW + hw0) * CN + c;

    float best = -INFINITY;
    int   bidx = hw0;

    #pragma unroll
    for (int i = 0; i < HWPA; ++i) {
        float v = x[base + (size_t)i * CN];
        if (v > best) {            // strict > + ascending i => first occurrence
            best = v;
            bidx = hw0 + i;
        }
    }

    const int o = (b * SA + s) * CN + c;
    g_pval[o] = best;
    g_pidx[o] = bidx;
}

// ---------------------------------------------------------------------------
// Kernel 2: combine 28 partials once per (b,c) -> g_idx (131 KB).
// Ascending p <=> ascending hw + strict > => first occurrence (jnp.argmax).
// ---------------------------------------------------------------------------
__global__ void __launch_bounds__(256)
combine_kernel() {
    const int tid = blockIdx.x * 256 + threadIdx.x;   // 0 .. 32767
    const int b = tid >> 9;
    const int c = tid & 511;

    const size_t o0 = (size_t)b * SA * CN + c;
    float best = -INFINITY;
    int   idx  = 0;
    #pragma unroll
    for (int p = 0; p < SA; ++p) {
        float v = g_pval[o0 + (size_t)p * CN];
        if (v > best) { best = v; idx = g_pidx[o0 + (size_t)p * CN]; }
    }
    g_idx[tid] = idx;
}

// ---------------------------------------------------------------------------
// Kernel 3: apply with channel-tiled smem template staging.
// Block = (b, ctile, s): 128 channels x 112 hw.
// Phase A: stage t_p[b, idx[c], s*112..+111] for the 128 channels with
//          COALESCED reads (rows contiguous in hw; 448B runs per row).
// Phase B: out = relu(x * st[c][hw]); x/out coalesced along c (warp = 32
//          consecutive channels = 128B), templates from conflict-free smem.
// ---------------------------------------------------------------------------
__global__ void __launch_bounds__(512, 3)
apply_kernel(const float* __restrict__ x,
             const float* __restrict__ tp,
             float* __restrict__ out) {
    extern __shared__ float st[];          // [CPB][PAD] = 57856 B
    __shared__ int sidx[CPB];

    const int q  = blockIdx.x;             // 0..27
    const int b  = blockIdx.y;
    const int ct = q / SB;                 // 0..3
    const int s  = q - ct * SB;            // 0..6
    const int tid     = threadIdx.x;
    const int c_local = tid & (CPB - 1);   // 0..127
    const int sub     = tid >> 7;          // 0..3

    if (tid < CPB) sidx[tid] = g_idx[b * CN + ct * CPB + tid];
    __syncthreads();

    // Phase A: stage 128 rows x 112 floats. Consecutive threads read
    // consecutive hw of the same row -> coalesced 128B requests.
    const size_t tb = (size_t)b * HW;
    #pragma unroll 7
    for (int e = tid; e < CPB * HWPB; e += 512) {
        const int r = e / HWPB;
        const int i = e - r * HWPB;
        st[r * PAD + i] = tp[(tb + (size_t)sidx[r]) * HW + s * HWPB + i];
    }
    __syncthreads();

    // Phase B: multiply + relu.
    const int hwl = sub * HWS;
    const size_t base =
        ((size_t)b * HW + (size_t)s * HWPB + hwl) * CN + ct * CPB + c_local;
    const float* __restrict__ tc = st + c_local * PAD + hwl;

    #pragma unroll 4
    for (int i = 0; i < HWS; ++i) {
        float xv = x[base + (size_t)i * CN];
        out[base + (size_t)i * CN] = fmaxf(xv * tc[i], 0.0f);
    }
}

// ---------------------------------------------------------------------------
// Launch: inputs [x, t_p]; output fp32 [64,28,28,512]. Graph-capturable.
// ---------------------------------------------------------------------------
extern "C" void kernel_launch(void* const* d_in, const int* in_sizes, int n_in,
                              void* d_out, int out_size) {
    (void)in_sizes; (void)n_in; (void)out_size;
    const float* x   = (const float*)d_in[0];
    const float* tp  = (const float*)d_in[1];
    float*       out = (float*)d_out;

    const int smem_bytes = CPB * PAD * sizeof(float);   // 57856
    cudaFuncSetAttribute(apply_kernel,
                         cudaFuncAttributeMaxDynamicSharedMemorySize, smem_bytes);

    dim3 gridA(SA, BN);
    argmax_partial_kernel<<<gridA, CN>>>(x);

    combine_kernel<<<128, 256>>>();

    dim3 gridB(CT * SB, BN);
    apply_kernel<<<gridB, 512, smem_bytes>>>(x, tp, out);
}

// round 10
// speedup vs baseline: 1.4691x; 1.4691x over previous
#include <cuda_runtime.h>
#include <math.h>

// Problem constants
#define BN    64
#define HW    784           // 28*28
#define CN    512
#define SA    28            // argmax hw splits  (HWPA = 28)
#define HWPA  28
#define SB    7             // apply hw splits   (HWPB = 112; 448B ≡ 0 mod 16)
#define HWPB  112
#define HWPB4 28            // HWPB / 4

// Scratch (device globals: allocation-free)
__device__ float g_pval[BN * SA * CN];
__device__ int   g_pidx[BN * SA * CN];
__device__ int   g_idx [BN * CN];

// ---------------------------------------------------------------------------
// Kernel 1: partial argmax (proven 4x: 19.5us, DRAM 67%).
// blockIdx = (s, b); thread = channel. Coalesced scalar reads, full unroll.
// ---------------------------------------------------------------------------
__global__ void __launch_bounds__(CN)
argmax_partial_kernel(const float* __restrict__ x) {
    const int s = blockIdx.x;
    const int b = blockIdx.y;
    const int c = threadIdx.x;
    const int hw0 = s * HWPA;

    const size_t base = ((size_t)b * HW + hw0) * CN + c;

    float best = -INFINITY;
    int   bidx = hw0;

    #pragma unroll
    for (int i = 0; i < HWPA; ++i) {
        float v = x[base + (size_t)i * CN];
        if (v > best) {            // strict > + ascending i => first occurrence
            best = v;
            bidx = hw0 + i;
        }
    }

    const int o = (b * SA + s) * CN + c;
    g_pval[o] = best;
    g_pidx[o] = bidx;
}

// ---------------------------------------------------------------------------
// Kernel 2: combine 28 partials once per (b,c) -> g_idx (131 KB, ~2.5us).
// Ascending p <=> ascending hw + strict > => first occurrence (jnp.argmax).
// ---------------------------------------------------------------------------
__global__ void __launch_bounds__(256)
combine_kernel() {
    const int tid = blockIdx.x * 256 + threadIdx.x;   // 0 .. 32767
    const int b = tid >> 9;
    const int c = tid & 511;

    const size_t o0 = (size_t)b * SA * CN + c;
    float best = -INFINITY;
    int   idx  = 0;
    #pragma unroll
    for (int p = 0; p < SA; ++p) {
        float v = g_pval[o0 + (size_t)p * CN];
        if (v > best) { best = v; idx = g_pidx[o0 + (size_t)p * CN]; }
    }
    g_idx[tid] = idx;
}

// ---------------------------------------------------------------------------
// Kernel 3: apply — R2's measured-best loop VERBATIM (unroll 4, __ldg on
// templates, plain x loads / plain stores, regs ~32, 4 CTA/SM), with the
// combine prologue replaced by one coalesced g_idx read. No cache hints
// (R8 showed __ldcs/__stcs cost ~10us of x L2 hits).
// ---------------------------------------------------------------------------
__global__ void __launch_bounds__(CN)
apply_kernel(const float* __restrict__ x,
             const float* __restrict__ tp,
             float* __restrict__ out) {
    const int b = blockIdx.x;
    const int s = blockIdx.y;
    const int c = threadIdx.x;

    const int idx = g_idx[b * CN + c];    // 131 KB table, L2-hot, coalesced

    // Selected template row slice: t_p[b, idx, s*112 .. s*112+111]
    // Row pitch 3136B and slice offset 448B are 16B multiples -> float4-safe.
    const float4* __restrict__ trow4 =
        (const float4*)(tp + ((size_t)b * HW + (size_t)idx) * HW + s * HWPB);

    const size_t base = ((size_t)b * HW + (size_t)s * HWPB) * CN + c;

    #pragma unroll 4
    for (int j = 0; j < HWPB4; ++j) {
        const float4 t4 = __ldg(trow4 + j);
        const size_t o  = base + (size_t)(4 * j) * CN;

        float x0 = x[o];
        float x1 = x[o + (size_t)CN];
        float x2 = x[o + (size_t)(2 * CN)];
        float x3 = x[o + (size_t)(3 * CN)];

        out[o]                    = fmaxf(x0 * t4.x, 0.0f);
        out[o + (size_t)CN]       = fmaxf(x1 * t4.y, 0.0f);
        out[o + (size_t)(2 * CN)] = fmaxf(x2 * t4.z, 0.0f);
        out[o + (size_t)(3 * CN)] = fmaxf(x3 * t4.w, 0.0f);
    }
}

// ---------------------------------------------------------------------------
// Launch: inputs [x, t_p]; output fp32 [64,28,28,512]. Graph-capturable.
// ---------------------------------------------------------------------------
extern "C" void kernel_launch(void* const* d_in, const int* in_sizes, int n_in,
                              void* d_out, int out_size) {
    (void)in_sizes; (void)n_in; (void)out_size;
    const float* x   = (const float*)d_in[0];
    const float* tp  = (const float*)d_in[1];
    float*       out = (float*)d_out;

    dim3 gridA(SA, BN);
    argmax_partial_kernel<<<gridA, CN>>>(x);

    combine_kernel<<<128, 256>>>();

    dim3 gridB(BN, SB);
    apply_kernel<<<gridB, CN>>>(x, tp, out);
}